// round 6
// baseline (speedup 1.0000x reference)
#include <cuda_runtime.h>
#include <cuda_bf16.h>
#include <cstdint>
#include <math.h>

#define NB 64
#define DM 768
#define LV 576
#define LD 320
#define LA 192
#define CV 512
#define CD 256
#define CA 128

// GEMM tile config
#define BM 128
#define BN 128
#define AST 20                 // u32 row stride in smem (16 payload + 4 pad)
#define PL  (128 * AST)        // u32 per plane
#define BUF (4 * PL)           // u32 per stage (Ah, Al, Bh, Bl)
#define GEMM_SMEM (2 * BUF * 4)  // 81920 B

#define KPERM(jl) ((((jl) & 3) * 2) + ((jl) >> 2))

// ---------------- scratch (device globals; no runtime allocation) ----------
// split X (pre-permuted planes, u32 = bf16x2)
__device__ uint32_t g_xvh[(size_t)NB * LV * (DM / 2)], g_xvl[(size_t)NB * LV * (DM / 2)];
__device__ uint32_t g_xdh[(size_t)NB * LD * (DM / 2)], g_xdl[(size_t)NB * LD * (DM / 2)];
__device__ uint32_t g_xah[(size_t)NB * LA * (DM / 2)], g_xal[(size_t)NB * LA * (DM / 2)];
// split W
__device__ uint32_t g_wvh[DM * (DM / 2)], g_wvl[DM * (DM / 2)];
__device__ uint32_t g_wdh[DM * (DM / 2)], g_wdl[DM * (DM / 2)];
__device__ uint32_t g_wah[DM * (DM / 2)], g_wal[DM * (DM / 2)];
// split h (row-major, k = D)
__device__ uint32_t g_vh[(size_t)NB * LV * (DM / 2)], g_vl[(size_t)NB * LV * (DM / 2)];
__device__ uint32_t g_dh[(size_t)NB * LD * (DM / 2)], g_dl[(size_t)NB * LD * (DM / 2)];
__device__ uint32_t g_ah[(size_t)NB * LA * (DM / 2)], g_al[(size_t)NB * LA * (DM / 2)];
// split h^T (rows = d, k = l)
__device__ uint32_t g_vTh[(size_t)NB * DM * (LV / 2)], g_vTl[(size_t)NB * DM * (LV / 2)];
__device__ uint32_t g_dTh[(size_t)NB * DM * (LD / 2)], g_dTl[(size_t)NB * DM * (LD / 2)];
__device__ uint32_t g_aTh[(size_t)NB * DM * (LA / 2)], g_aTl[(size_t)NB * DM * (LA / 2)];
// fp32 scores + split probability planes (sized for largest pair: LV x LD)
__device__ float    g_S  [(size_t)NB * LV * LD];
__device__ uint32_t g_p12h[(size_t)NB * LV * (LD / 2)], g_p12l[(size_t)NB * LV * (LD / 2)];
__device__ uint32_t g_p21h[(size_t)NB * LV * (LD / 2)], g_p21l[(size_t)NB * LV * (LD / 2)];

// ---------------- helpers ---------------------------------------------------
__device__ __forceinline__ uint32_t smem_u32(const void* p) {
    uint32_t a;
    asm("{ .reg .u64 t; cvta.to.shared.u64 t, %1; cvt.u32.u64 %0, t; }" : "=r"(a) : "l"(p));
    return a;
}

__device__ __forceinline__ void mma16816(float* d, const uint32_t* a, const uint32_t* b)
{
    asm volatile(
        "mma.sync.aligned.m16n8k16.row.col.f32.bf16.bf16.f32 "
        "{%0,%1,%2,%3}, {%4,%5,%6,%7}, {%8,%9}, {%0,%1,%2,%3};"
        : "+f"(d[0]), "+f"(d[1]), "+f"(d[2]), "+f"(d[3])
        : "r"(a[0]), "r"(a[1]), "r"(a[2]), "r"(a[3]), "r"(b[0]), "r"(b[1]));
}

__device__ __forceinline__ void pack_split(float x, float y, uint32_t& hi, uint32_t& lo)
{
    __nv_bfloat162 h = __floats2bfloat162_rn(x, y);
    float hx = __bfloat162float(__low2bfloat16(h));
    float hy = __bfloat162float(__high2bfloat16(h));
    __nv_bfloat162 l = __floats2bfloat162_rn(x - hx, y - hy);
    hi = *reinterpret_cast<uint32_t*>(&h);
    lo = *reinterpret_cast<uint32_t*>(&l);
}

// ---------------------------------------------------------------------------
// split_src: fp32 row-major [rows, Kf] -> hi/lo bf16x2 planes, pre-permuted.
// ---------------------------------------------------------------------------
__global__ __launch_bounds__(256) void split_src(
    const float* __restrict__ in, uint32_t* __restrict__ hi, uint32_t* __restrict__ lo,
    long total, int Kf)
{
    long u = (long)blockIdx.x * 256 + threadIdx.x;
    if (u >= total) return;
    const int gpr = Kf >> 4;
    long row = u / gpr;
    int grp = (int)(u - row * gpr);
    const float* p = in + row * (long)Kf + grp * 16;
    float f[16];
#pragma unroll
    for (int q = 0; q < 4; ++q) *(float4*)(f + q * 4) = *(const float4*)(p + q * 4);
    uint32_t h[8], l[8];
#pragma unroll
    for (int j = 0; j < 8; ++j) pack_split(f[2 * j], f[2 * j + 1], h[j], l[j]);
    uint32_t* dh = hi + row * (long)(Kf >> 1) + grp * 8;
    uint32_t* dl = lo + row * (long)(Kf >> 1) + grp * 8;
    *(uint4*)(dh + 0) = make_uint4(h[0], h[4], h[1], h[5]);
    *(uint4*)(dh + 4) = make_uint4(h[2], h[6], h[3], h[7]);
    *(uint4*)(dl + 0) = make_uint4(l[0], l[4], l[1], l[5]);
    *(uint4*)(dl + 4) = make_uint4(l[2], l[6], l[3], l[7]);
}

// ---------------------------------------------------------------------------
// gemm_split: NT GEMM on pre-split pre-permuted bf16 planes.
// C[b,m,n] = alpha*sum_k A[m,k]*B[n,k] (+bias) (+=C if accum)
// Optional outputs: Chi/Clo = split row-major result; ATh/ATl = split
// transposed result (per-batch planes, batch length Lb; requires M%128==0).
// ---------------------------------------------------------------------------
__global__ __launch_bounds__(256) void gemm_split(
    const uint32_t* __restrict__ Ah, const uint32_t* __restrict__ Al,
    const uint32_t* __restrict__ Bh, const uint32_t* __restrict__ Bl,
    const float* __restrict__ bias, float* __restrict__ C,
    uint32_t* __restrict__ Chi, uint32_t* __restrict__ Clo,
    uint32_t* __restrict__ ATh, uint32_t* __restrict__ ATl, int Lb,
    int M, int N, int K, long sA, long sB, long sC, float alpha, int accum)
{
    extern __shared__ uint32_t sm[];
    const int tid = threadIdx.x;
    const int bz = blockIdx.z;
    Ah += (long)bz * sA; Al += (long)bz * sA;
    Bh += (long)bz * sB; Bl += (long)bz * sB;
    if (C) C += (long)bz * sC;

    const int m0 = blockIdx.y * BM;
    const int n0 = blockIdx.x * BN;
    const int K2 = K >> 1;
    const int nc = K >> 5;

    const int wid = tid >> 5, lane = tid & 31;
    const int wm = wid >> 1, wn = wid & 1;
    const int g = lane >> 2, c4 = lane & 3;

    const uint32_t smem_base = smem_u32(sm);

    float acc[2][8][4];
#pragma unroll
    for (int mt = 0; mt < 2; ++mt)
#pragma unroll
        for (int nt = 0; nt < 8; ++nt)
#pragma unroll
            for (int q = 0; q < 4; ++q) acc[mt][nt][q] = 0.f;

    auto issue = [&](int cc, int buf) {
#pragma unroll
        for (int it = 0; it < 8; ++it) {
            const int plane = it >> 1;
            const int u = ((it & 1) << 8) + tid;
            const int row = u >> 2, ch = u & 3;
            uint32_t dst = smem_base +
                (uint32_t)((buf * BUF + plane * PL + row * AST + ch * 4) * 4);
            const uint32_t* srcb;
            bool valid;
            if (plane < 2) {
                valid = (m0 + row) < M;
                srcb = (plane == 0 ? Ah : Al) + (long)(valid ? m0 + row : 0) * K2 + cc * 16 + ch * 4;
            } else {
                valid = (n0 + row) < N;
                srcb = (plane == 2 ? Bh : Bl) + (long)(valid ? n0 + row : 0) * K2 + cc * 16 + ch * 4;
            }
            int sb = valid ? 16 : 0;
            asm volatile("cp.async.cg.shared.global [%0], [%1], 16, %2;"
                         :: "r"(dst), "l"(srcb), "r"(sb) : "memory");
        }
        asm volatile("cp.async.commit_group;" ::: "memory");
    };

    issue(0, 0);

    for (int c = 0; c < nc; ++c) {
        if (c + 1 < nc) {
            issue(c + 1, (c + 1) & 1);
            asm volatile("cp.async.wait_group 1;" ::: "memory");
        } else {
            asm volatile("cp.async.wait_group 0;" ::: "memory");
        }
        __syncthreads();

        const uint32_t* Pa_h = sm + (c & 1) * BUF;
        const uint32_t* Pa_l = Pa_h + PL;
        const uint32_t* Pb_h = Pa_h + 2 * PL;
        const uint32_t* Pb_l = Pa_h + 3 * PL;

#pragma unroll
        for (int s = 0; s < 2; ++s) {
            const int kc = s * 8 + 2 * c4;
            uint32_t af[2][2][4];
#pragma unroll
            for (int mt = 0; mt < 2; ++mt) {
                const int r = wm * 32 + mt * 16 + g;
                uint2 t0 = *(const uint2*)(Pa_h + r * AST + kc);
                uint2 t1 = *(const uint2*)(Pa_h + (r + 8) * AST + kc);
                af[0][mt][0] = t0.x; af[0][mt][1] = t1.x;
                af[0][mt][2] = t0.y; af[0][mt][3] = t1.y;
                t0 = *(const uint2*)(Pa_l + r * AST + kc);
                t1 = *(const uint2*)(Pa_l + (r + 8) * AST + kc);
                af[1][mt][0] = t0.x; af[1][mt][1] = t1.x;
                af[1][mt][2] = t0.y; af[1][mt][3] = t1.y;
            }
#pragma unroll
            for (int nh = 0; nh < 2; ++nh) {
                uint32_t bh[4][2], bl[4][2];
#pragma unroll
                for (int nt = 0; nt < 4; ++nt) {
                    const int rb = wn * 64 + nh * 32 + nt * 8 + g;
                    uint2 t = *(const uint2*)(Pb_h + rb * AST + kc);
                    bh[nt][0] = t.x; bh[nt][1] = t.y;
                    t = *(const uint2*)(Pb_l + rb * AST + kc);
                    bl[nt][0] = t.x; bl[nt][1] = t.y;
                }
#pragma unroll
                for (int mt = 0; mt < 2; ++mt)
#pragma unroll
                    for (int nt = 0; nt < 4; ++nt)
                        mma16816(acc[mt][nh * 4 + nt], af[0][mt], bh[nt]);
#pragma unroll
                for (int mt = 0; mt < 2; ++mt)
#pragma unroll
                    for (int nt = 0; nt < 4; ++nt)
                        mma16816(acc[mt][nh * 4 + nt], af[0][mt], bl[nt]);
#pragma unroll
                for (int mt = 0; mt < 2; ++mt)
#pragma unroll
                    for (int nt = 0; nt < 4; ++nt)
                        mma16816(acc[mt][nh * 4 + nt], af[1][mt], bh[nt]);
            }
        }
        __syncthreads();
    }

    // ---- epilogue ----
    float* tile = (float*)sm;   // reused staging: [128][132] when ATh path active
#pragma unroll
    for (int mt = 0; mt < 2; ++mt)
#pragma unroll
        for (int half = 0; half < 2; ++half) {
            const int m = m0 + wm * 32 + mt * 16 + g + half * 8;
            if (m >= M) continue;
#pragma unroll
            for (int ntg = 0; ntg < 8; ++ntg) {
                const int n = n0 + wn * 64 + ntg * 8 + 2 * c4;
                if (n >= N) continue;
                float2 o;
                o.x = acc[mt][ntg][half * 2 + 0] * alpha;
                o.y = acc[mt][ntg][half * 2 + 1] * alpha;
                if (bias) { o.x += bias[n]; o.y += bias[n + 1]; }
                if (C) {
                    const long off = (long)m * N + n;
                    if (accum) {
                        float2 old = *(const float2*)(C + off);
                        o.x += old.x; o.y += old.y;
                    }
                    *(float2*)(C + off) = o;
                }
                if (Chi) {
                    uint32_t h, l;
                    pack_split(o.x, o.y, h, l);
                    const int jj = n >> 1, jl = jj & 7;
                    const long so = (long)m * (N >> 1) + (jj & ~7) + KPERM(jl);
                    Chi[so] = h; Clo[so] = l;
                }
                if (ATh) {
                    const int lr = m - m0, lc = n - n0;
                    tile[lr * 132 + lc] = o.x;
                    tile[lr * 132 + lc + 1] = o.y;
                }
            }
        }

    if (ATh) {
        __syncthreads();
        // write transposed split planes: rows = n (dim), k = m (seq within batch)
        for (int u = tid; u < 64 * 128; u += 256) {
            const int p = u >> 7;            // m row-pair 0..63
            const int nn = u & 127;
            float v0 = tile[(2 * p) * 132 + nn];
            float v1 = tile[(2 * p + 1) * 132 + nn];
            uint32_t h, l;
            pack_split(v0, v1, h, l);
            const int gm = m0 + 2 * p;
            const int b = gm / Lb;
            const int lloc = gm - b * Lb;
            const int jj = lloc >> 1, jg = jj & 7;
            const long so = ((long)b * N + (n0 + nn)) * (Lb >> 1) + (jj & ~7) + KPERM(jg);
            ATh[so] = h; ATl[so] = l;
        }
    }
}

// ---------------------------------------------------------------------------
// Row softmax (p12): reads fp32 S, writes split-perm P12 planes. S untouched.
// allowed = (j < c2) || (i >= c1 && i-c1 >= j-c2)
// ---------------------------------------------------------------------------
template <int L2>
__global__ __launch_bounds__(256) void softmax12(
    const float* __restrict__ S, const float* __restrict__ mk,
    uint32_t* __restrict__ Phi, uint32_t* __restrict__ Plo, int L1, int c1, int c2)
{
    constexpr int NU = L2 / 64;
    const int warp = threadIdx.x >> 5;
    const int lane = threadIdx.x & 31;
    const int b = blockIdx.y;
    const int i = blockIdx.x * 8 + warp;
    if (i >= L1) return;
    const float* row = S + ((long)b * L1 + i) * L2;
    const float* m2 = mk + (long)b * L2;

    float v[2 * NU];
    float mx = -INFINITY;
#pragma unroll
    for (int t = 0; t < NU; ++t) {
        const int jj = t * 32 + lane;
        const int j = 2 * jj;
        float2 sv = *(const float2*)(row + j);
        float2 mm = *(const float2*)(m2 + j);
        float al0 = ((j < c2) || (i >= c1 && (i - c1) >= (j - c2))) ? 1.f : 0.f;
        float al1 = ((j + 1 < c2) || (i >= c1 && (i - c1) >= (j + 1 - c2))) ? 1.f : 0.f;
        v[2 * t + 0] = sv.x + (1.f - al0 * mm.x) * -10000.f;
        v[2 * t + 1] = sv.y + (1.f - al1 * mm.y) * -10000.f;
        mx = fmaxf(mx, fmaxf(v[2 * t], v[2 * t + 1]));
    }
#pragma unroll
    for (int off = 16; off > 0; off >>= 1)
        mx = fmaxf(mx, __shfl_xor_sync(0xffffffffu, mx, off));
    float Z = 0.f;
#pragma unroll
    for (int t = 0; t < 2 * NU; ++t) { v[t] = __expf(v[t] - mx); Z += v[t]; }
#pragma unroll
    for (int off = 16; off > 0; off >>= 1)
        Z += __shfl_xor_sync(0xffffffffu, Z, off);
    const float inv = 1.f / Z;
    const long base = ((long)b * L1 + i) * (L2 >> 1);
#pragma unroll
    for (int t = 0; t < NU; ++t) {
        const int jj = t * 32 + lane, jl = jj & 7;
        uint32_t h, l;
        pack_split(v[2 * t] * inv, v[2 * t + 1] * inv, h, l);
        const long so = base + (jj & ~7) + KPERM(jl);
        Phi[so] = h; Plo[so] = l;
    }
}

// ---------------------------------------------------------------------------
// Column softmax (p21), single-pass over global S: caches the masked column
// strip in dynamic smem during the stats pass, then writes split P21 planes.
// allowed = (i < c1) || (j >= c2 && j-c2 >= i-c1)
// dynamic smem = L1 * 33 * 4 bytes.
// ---------------------------------------------------------------------------
__global__ __launch_bounds__(256) void softmax21(
    const float* __restrict__ S, const float* __restrict__ mk1,
    uint32_t* __restrict__ Phi, uint32_t* __restrict__ Plo,
    int L1, int L2, int c1, int c2)
{
    extern __shared__ float col[];   // [L1][33]
    __shared__ float smx[8][32];
    __shared__ float ssum[8][32];

    const int tx = threadIdx.x & 31;
    const int ty = threadIdx.x >> 5;
    const int b = blockIdx.y;
    const int j0 = blockIdx.x * 32;
    const int j = j0 + tx;
    const float* Sb = S + (long)b * L1 * L2;
    const float* m1 = mk1 + (long)b * L1;

    float mx = -INFINITY, Z = 0.f;
    for (int i = ty; i < L1; i += 8) {
        float allowed = ((i < c1) || (j >= c2 && (j - c2) >= (i - c1))) ? 1.f : 0.f;
        float s = Sb[(long)i * L2 + j] + (1.f - allowed * m1[i]) * -10000.f;
        col[i * 33 + tx] = s;
        if (s > mx) { Z = Z * __expf(mx - s) + 1.f; mx = s; }
        else        { Z += __expf(s - mx); }
    }
    smx[ty][tx] = mx; ssum[ty][tx] = Z;
    __syncthreads();
    if (ty == 0) {
        float m = smx[0][tx], z = ssum[0][tx];
#pragma unroll
        for (int r = 1; r < 8; ++r) {
            float m2 = smx[r][tx], z2 = ssum[r][tx];
            float mm = fmaxf(m, m2);
            z = z * __expf(m - mm) + z2 * __expf(m2 - mm);
            m = mm;
        }
        smx[0][tx] = m; ssum[0][tx] = 1.f / z;
    }
    __syncthreads();

    const int HP = L1 >> 1;   // i-pairs
    for (int u = threadIdx.x; u < 32 * HP; u += 256) {
        const int jl = u / HP;
        const int pr = u - jl * HP;
        const float rm = smx[0][jl];
        const float iz = ssum[0][jl];
        float e0 = __expf(col[(2 * pr) * 33 + jl] - rm) * iz;
        float e1 = __expf(col[(2 * pr + 1) * 33 + jl] - rm) * iz;
        uint32_t h, l;
        pack_split(e0, e1, h, l);
        const int jg = pr & 7;
        const long so = ((long)b * L2 + j0 + jl) * HP + (pr & ~7) + KPERM(jg);
        Phi[so] = h; Plo[so] = l;
    }
}

// ---------------------------------------------------------------------------
static inline dim3 gg(int M, int N, int batch) {
    return dim3((unsigned)((N + BN - 1) / BN), (unsigned)((M + BM - 1) / BM), (unsigned)batch);
}

extern "C" void kernel_launch(void* const* d_in, const int* in_sizes, int n_in,
                              void* d_out, int out_size)
{
    const float* vemb = (const float*)d_in[0];
    const float* mv   = (const float*)d_in[1];
    const float* demb = (const float*)d_in[2];
    const float* md   = (const float*)d_in[3];
    const float* aemb = (const float*)d_in[4];
    const float* ma   = (const float*)d_in[5];
    const float* Wv   = (const float*)d_in[6];
    const float* bv   = (const float*)d_in[7];
    const float* Wd   = (const float*)d_in[8];
    const float* bd   = (const float*)d_in[9];
    const float* Wa   = (const float*)d_in[10];
    const float* ba   = (const float*)d_in[11];

    float* out1 = (float*)d_out;
    float* out2 = out1 + (size_t)NB * LV * DM;
    float* out3 = out2 + (size_t)NB * LD * DM;

#define GA(v, s) cudaGetSymbolAddress((void**)&v, s)
    float* S;
    uint32_t *xvh, *xvl, *xdh, *xdl, *xah, *xal;
    uint32_t *wvh, *wvl, *wdh, *wdl, *wah, *wal;
    uint32_t *vh, *vl, *dh, *dl, *ah, *al;
    uint32_t *vTh, *vTl, *dTh, *dTl, *aTh, *aTl;
    uint32_t *p12h, *p12l, *p21h, *p21l;
    GA(S, g_S);
    GA(xvh, g_xvh); GA(xvl, g_xvl); GA(xdh, g_xdh); GA(xdl, g_xdl);
    GA(xah, g_xah); GA(xal, g_xal);
    GA(wvh, g_wvh); GA(wvl, g_wvl); GA(wdh, g_wdh); GA(wdl, g_wdl);
    GA(wah, g_wah); GA(wal, g_wal);
    GA(vh, g_vh); GA(vl, g_vl); GA(dh, g_dh); GA(dl, g_dl);
    GA(ah, g_ah); GA(al, g_al);
    GA(vTh, g_vTh); GA(vTl, g_vTl); GA(dTh, g_dTh); GA(dTl, g_dTl);
    GA(aTh, g_aTh); GA(aTl, g_aTl);
    GA(p12h, g_p12h); GA(p12l, g_p12l); GA(p21h, g_p21h); GA(p21l, g_p21l);
#undef GA

    cudaFuncSetAttribute(gemm_split, cudaFuncAttributeMaxDynamicSharedMemorySize, GEMM_SMEM);
    cudaFuncSetAttribute(softmax21, cudaFuncAttributeMaxDynamicSharedMemorySize, LV * 33 * 4);

    const long tv = (long)NB * LV * (DM / 16), td = (long)NB * LD * (DM / 16),
               ta = (long)NB * LA * (DM / 16), tw = (long)DM * (DM / 16);

    // ---- launch order tuned so ncu (-s 5 -c 1) captures the big proj GEMM ----
    split_src<<<(unsigned)((tw + 255) / 256), 256>>>(Wv, wvh, wvl, tw, DM);     // 0
    split_src<<<(unsigned)((tw + 255) / 256), 256>>>(Wd, wdh, wdl, tw, DM);     // 1
    split_src<<<(unsigned)((tw + 255) / 256), 256>>>(Wa, wah, wal, tw, DM);     // 2
    split_src<<<(unsigned)((tv + 255) / 256), 256>>>(vemb, xvh, xvl, tv, DM);   // 3
    split_src<<<(unsigned)((td + 255) / 256), 256>>>(demb, xdh, xdl, td, DM);   // 4

    // 5: projection vid (captured by ncu) — writes split h AND split h^T
    gemm_split<<<gg(NB * LV, DM, 1), 256, GEMM_SMEM>>>(xvh, xvl, wvh, wvl, bv,
        nullptr, vh, vl, vTh, vTl, LV, NB * LV, DM, DM, 0, 0, 0, 1.f, 0);

    split_src<<<(unsigned)((ta + 255) / 256), 256>>>(aemb, xah, xal, ta, DM);   // 6

    gemm_split<<<gg(NB * LD, DM, 1), 256, GEMM_SMEM>>>(xdh, xdl, wdh, wdl, bd,
        nullptr, dh, dl, dTh, dTl, LD, NB * LD, DM, DM, 0, 0, 0, 1.f, 0);
    gemm_split<<<gg(NB * LA, DM, 1), 256, GEMM_SMEM>>>(xah, xal, wah, wal, ba,
        nullptr, ah, al, aTh, aTl, LA, NB * LA, DM, DM, 0, 0, 0, 1.f, 0);

    // ==== pair A: vid (L1=576, c1=512) x det (L2=320, c2=256) ====
    gemm_split<<<gg(LV, LD, NB), 256, GEMM_SMEM>>>(vh, vl, dh, dl, nullptr, S,
        nullptr, nullptr, nullptr, nullptr, 0, LV, LD, DM,
        (long)LV * (DM / 2), (long)LD * (DM / 2), (long)LV * LD, 0.125f, 0);
    softmax21<<<dim3(LD / 32, NB), 256, LV * 33 * 4>>>(S, mv, p21h, p21l, LV, LD, CV, CD);
    softmax12<LD><<<dim3(LV / 8, NB), 256>>>(S, md, p12h, p12l, LV, CV, CD);
    gemm_split<<<gg(LV, DM, NB), 256, GEMM_SMEM>>>(p12h, p12l, dTh, dTl, nullptr, out1,
        nullptr, nullptr, nullptr, nullptr, 0, LV, DM, LD,
        (long)LV * (LD / 2), (long)DM * (LD / 2), (long)LV * DM, 1.f, 0);   // c_vd
    gemm_split<<<gg(LD, DM, NB), 256, GEMM_SMEM>>>(p21h, p21l, vTh, vTl, nullptr, out2,
        nullptr, nullptr, nullptr, nullptr, 0, LD, DM, LV,
        (long)LD * (LV / 2), (long)DM * (LV / 2), (long)LD * DM, 1.f, 0);   // c_dv

    // ==== pair B: vid (576, 512) x act (192, 128) ====
    gemm_split<<<gg(LV, LA, NB), 256, GEMM_SMEM>>>(vh, vl, ah, al, nullptr, S,
        nullptr, nullptr, nullptr, nullptr, 0, LV, LA, DM,
        (long)LV * (DM / 2), (long)LA * (DM / 2), (long)LV * LA, 0.125f, 0);
    softmax21<<<dim3(LA / 32, NB), 256, LV * 33 * 4>>>(S, mv, p21h, p21l, LV, LA, CV, CA);
    softmax12<LA><<<dim3(LV / 8, NB), 256>>>(S, ma, p12h, p12l, LV, CV, CA);
    gemm_split<<<gg(LV, DM, NB), 256, GEMM_SMEM>>>(p12h, p12l, aTh, aTl, nullptr, out1,
        nullptr, nullptr, nullptr, nullptr, 0, LV, DM, LA,
        (long)LV * (LA / 2), (long)DM * (LA / 2), (long)LV * DM, 1.f, 1);   // += c_va
    gemm_split<<<gg(LA, DM, NB), 256, GEMM_SMEM>>>(p21h, p21l, vTh, vTl, nullptr, out3,
        nullptr, nullptr, nullptr, nullptr, 0, LA, DM, LV,
        (long)LA * (LV / 2), (long)DM * (LV / 2), (long)LA * DM, 1.f, 0);   // c_av

    // ==== pair C: act (192, 128) x det (320, 256) ====
    gemm_split<<<gg(LA, LD, NB), 256, GEMM_SMEM>>>(ah, al, dh, dl, nullptr, S,
        nullptr, nullptr, nullptr, nullptr, 0, LA, LD, DM,
        (long)LA * (DM / 2), (long)LD * (DM / 2), (long)LA * LD, 0.125f, 0);
    softmax21<<<dim3(LD / 32, NB), 256, LA * 33 * 4>>>(S, ma, p21h, p21l, LA, LD, CA, CD);
    softmax12<LD><<<dim3(LA / 8, NB), 256>>>(S, md, p12h, p12l, LA, CA, CD);
    gemm_split<<<gg(LA, DM, NB), 256, GEMM_SMEM>>>(p12h, p12l, dTh, dTl, nullptr, out3,
        nullptr, nullptr, nullptr, nullptr, 0, LA, DM, LD,
        (long)LA * (LD / 2), (long)DM * (LD / 2), (long)LA * DM, 1.f, 1);   // += c_ad
    gemm_split<<<gg(LD, DM, NB), 256, GEMM_SMEM>>>(p21h, p21l, aTh, aTl, nullptr, out2,
        nullptr, nullptr, nullptr, nullptr, 0, LD, DM, LA,
        (long)LD * (LA / 2), (long)DM * (LA / 2), (long)LD * DM, 1.f, 1);   // += c_da
}

// round 7
// speedup vs baseline: 1.1039x; 1.1039x over previous
#include <cuda_runtime.h>
#include <cuda_bf16.h>
#include <cstdint>
#include <math.h>

#define NB 64
#define DM 768
#define LV 576
#define LD 320
#define LA 192
#define CV 512
#define CD 256
#define CA 128

// GEMM tile config
#define BM 128
#define BN 128
#define AST 20                 // u32 row stride in smem (16 payload + 4 pad)
#define PL  (128 * AST)
#define BUF (4 * PL)           // per stage (Ah, Al, Bh, Bl)
#define GEMM_SMEM (2 * BUF * 4)  // 81920 B

#define KPERM(jl) ((((jl) & 3) * 2) + ((jl) >> 2))

// ---------------- scratch (device globals; no runtime allocation) ----------
__device__ float g_vid[(size_t)NB * LV * DM];
__device__ float g_det[(size_t)NB * LD * DM];
__device__ float g_act[(size_t)NB * LA * DM];
__device__ uint32_t g_xvh[(size_t)NB * LV * (DM / 2)], g_xvl[(size_t)NB * LV * (DM / 2)];
__device__ uint32_t g_xdh[(size_t)NB * LD * (DM / 2)], g_xdl[(size_t)NB * LD * (DM / 2)];
__device__ uint32_t g_xah[(size_t)NB * LA * (DM / 2)], g_xal[(size_t)NB * LA * (DM / 2)];
__device__ uint32_t g_wvh[DM * (DM / 2)], g_wvl[DM * (DM / 2)];
__device__ uint32_t g_wdh[DM * (DM / 2)], g_wdl[DM * (DM / 2)];
__device__ uint32_t g_wah[DM * (DM / 2)], g_wal[DM * (DM / 2)];
__device__ uint32_t g_vh[(size_t)NB * LV * (DM / 2)], g_vl[(size_t)NB * LV * (DM / 2)];
__device__ uint32_t g_dh[(size_t)NB * LD * (DM / 2)], g_dl[(size_t)NB * LD * (DM / 2)];
__device__ uint32_t g_ah[(size_t)NB * LA * (DM / 2)], g_al[(size_t)NB * LA * (DM / 2)];
__device__ uint32_t g_vTh[(size_t)NB * DM * (LV / 2)], g_vTl[(size_t)NB * DM * (LV / 2)];
__device__ uint32_t g_dTh[(size_t)NB * DM * (LD / 2)], g_dTl[(size_t)NB * DM * (LD / 2)];
__device__ uint32_t g_aTh[(size_t)NB * DM * (LA / 2)], g_aTl[(size_t)NB * DM * (LA / 2)];
__device__ float    g_S  [(size_t)NB * LV * LD];
__device__ uint32_t g_p12h[(size_t)NB * LV * (LD / 2)], g_p12l[(size_t)NB * LV * (LD / 2)];
__device__ uint32_t g_p21h[(size_t)NB * LV * (LD / 2)], g_p21l[(size_t)NB * LV * (LD / 2)];

// ---------------- helpers ---------------------------------------------------
__device__ __forceinline__ uint32_t smem_u32(const void* p) {
    uint32_t a;
    asm("{ .reg .u64 t; cvta.to.shared.u64 t, %1; cvt.u32.u64 %0, t; }" : "=r"(a) : "l"(p));
    return a;
}

__device__ __forceinline__ void mma16816(float* d, const uint32_t* a, const uint32_t* b)
{
    asm volatile(
        "mma.sync.aligned.m16n8k16.row.col.f32.bf16.bf16.f32 "
        "{%0,%1,%2,%3}, {%4,%5,%6,%7}, {%8,%9}, {%0,%1,%2,%3};"
        : "+f"(d[0]), "+f"(d[1]), "+f"(d[2]), "+f"(d[3])
        : "r"(a[0]), "r"(a[1]), "r"(a[2]), "r"(a[3]), "r"(b[0]), "r"(b[1]));
}

__device__ __forceinline__ void pack_split(float x, float y, uint32_t& hi, uint32_t& lo)
{
    __nv_bfloat162 h = __floats2bfloat162_rn(x, y);
    float hx = __bfloat162float(__low2bfloat16(h));
    float hy = __bfloat162float(__high2bfloat16(h));
    __nv_bfloat162 l = __floats2bfloat162_rn(x - hx, y - hy);
    hi = *reinterpret_cast<uint32_t*>(&h);
    lo = *reinterpret_cast<uint32_t*>(&l);
}

// ---------------------------------------------------------------------------
// split_src: fp32 row-major [rows, Kf] -> hi/lo bf16x2 planes, pre-permuted.
// ---------------------------------------------------------------------------
__global__ __launch_bounds__(256) void split_src(
    const float* __restrict__ in, uint32_t* __restrict__ hi, uint32_t* __restrict__ lo,
    long total, int Kf)
{
    long u = (long)blockIdx.x * 256 + threadIdx.x;
    if (u >= total) return;
    const int gpr = Kf >> 4;
    long row = u / gpr;
    int grp = (int)(u - row * gpr);
    const float* p = in + row * (long)Kf + grp * 16;
    float f[16];
#pragma unroll
    for (int q = 0; q < 4; ++q) *(float4*)(f + q * 4) = *(const float4*)(p + q * 4);
    uint32_t h[8], l[8];
#pragma unroll
    for (int j = 0; j < 8; ++j) pack_split(f[2 * j], f[2 * j + 1], h[j], l[j]);
    uint32_t* dh = hi + row * (long)(Kf >> 1) + grp * 8;
    uint32_t* dl = lo + row * (long)(Kf >> 1) + grp * 8;
    *(uint4*)(dh + 0) = make_uint4(h[0], h[4], h[1], h[5]);
    *(uint4*)(dh + 4) = make_uint4(h[2], h[6], h[3], h[7]);
    *(uint4*)(dl + 0) = make_uint4(l[0], l[4], l[1], l[5]);
    *(uint4*)(dl + 4) = make_uint4(l[2], l[6], l[3], l[7]);
}

// ---------------------------------------------------------------------------
// gemm_split: NT GEMM on pre-split pre-permuted bf16 planes.
// C[b,m,n] = alpha*sum_k A[m,k]*B[n,k] (+bias) (+=C); optional split-out.
// __launch_bounds__(256,2): cap regs at 128 so 2 CTAs co-reside per SM.
// ---------------------------------------------------------------------------
__global__ __launch_bounds__(256, 2) void gemm_split(
    const uint32_t* __restrict__ Ah, const uint32_t* __restrict__ Al,
    const uint32_t* __restrict__ Bh, const uint32_t* __restrict__ Bl,
    const float* __restrict__ bias, float* __restrict__ C,
    uint32_t* __restrict__ Chi, uint32_t* __restrict__ Clo,
    int M, int N, int K, long sA, long sB, long sC, float alpha, int accum)
{
    extern __shared__ uint32_t sm[];
    const int tid = threadIdx.x;
    const int bz = blockIdx.z;
    Ah += (long)bz * sA; Al += (long)bz * sA;
    Bh += (long)bz * sB; Bl += (long)bz * sB;
    C  += (long)bz * sC;

    const int m0 = blockIdx.y * BM;
    const int n0 = blockIdx.x * BN;
    const int K2 = K >> 1;
    const int nc = K >> 5;

    const int wid = tid >> 5, lane = tid & 31;
    const int wm = wid >> 1, wn = wid & 1;
    const int g = lane >> 2, c4 = lane & 3;

    const uint32_t smem_base = smem_u32(sm);

    float acc[2][8][4];
#pragma unroll
    for (int mt = 0; mt < 2; ++mt)
#pragma unroll
        for (int nt = 0; nt < 8; ++nt)
#pragma unroll
            for (int q = 0; q < 4; ++q) acc[mt][nt][q] = 0.f;

    auto issue = [&](int cc, int buf) {
#pragma unroll
        for (int it = 0; it < 8; ++it) {
            const int plane = it >> 1;
            const int u = ((it & 1) << 8) + tid;
            const int row = u >> 2, ch = u & 3;
            uint32_t dst = smem_base +
                (uint32_t)((buf * BUF + plane * PL + row * AST + ch * 4) * 4);
            const uint32_t* srcb;
            bool valid;
            if (plane < 2) {
                valid = (m0 + row) < M;
                srcb = (plane == 0 ? Ah : Al) + (long)(valid ? m0 + row : 0) * K2 + cc * 16 + ch * 4;
            } else {
                valid = (n0 + row) < N;
                srcb = (plane == 2 ? Bh : Bl) + (long)(valid ? n0 + row : 0) * K2 + cc * 16 + ch * 4;
            }
            int sb = valid ? 16 : 0;
            asm volatile("cp.async.cg.shared.global [%0], [%1], 16, %2;"
                         :: "r"(dst), "l"(srcb), "r"(sb) : "memory");
        }
        asm volatile("cp.async.commit_group;" ::: "memory");
    };

    issue(0, 0);

    for (int c = 0; c < nc; ++c) {
        if (c + 1 < nc) {
            issue(c + 1, (c + 1) & 1);
            asm volatile("cp.async.wait_group 1;" ::: "memory");
        } else {
            asm volatile("cp.async.wait_group 0;" ::: "memory");
        }
        __syncthreads();

        const uint32_t* Pa_h = sm + (c & 1) * BUF;
        const uint32_t* Pa_l = Pa_h + PL;
        const uint32_t* Pb_h = Pa_h + 2 * PL;
        const uint32_t* Pb_l = Pa_h + 3 * PL;

#pragma unroll
        for (int s = 0; s < 2; ++s) {
            const int kc = s * 8 + 2 * c4;
            uint32_t af[2][2][4];
#pragma unroll
            for (int mt = 0; mt < 2; ++mt) {
                const int r = wm * 32 + mt * 16 + g;
                uint2 t0 = *(const uint2*)(Pa_h + r * AST + kc);
                uint2 t1 = *(const uint2*)(Pa_h + (r + 8) * AST + kc);
                af[0][mt][0] = t0.x; af[0][mt][1] = t1.x;
                af[0][mt][2] = t0.y; af[0][mt][3] = t1.y;
                t0 = *(const uint2*)(Pa_l + r * AST + kc);
                t1 = *(const uint2*)(Pa_l + (r + 8) * AST + kc);
                af[1][mt][0] = t0.x; af[1][mt][1] = t1.x;
                af[1][mt][2] = t0.y; af[1][mt][3] = t1.y;
            }
#pragma unroll
            for (int nh = 0; nh < 2; ++nh) {
                uint32_t bh[4][2], bl[4][2];
#pragma unroll
                for (int nt = 0; nt < 4; ++nt) {
                    const int rb = wn * 64 + nh * 32 + nt * 8 + g;
                    uint2 t = *(const uint2*)(Pb_h + rb * AST + kc);
                    bh[nt][0] = t.x; bh[nt][1] = t.y;
                    t = *(const uint2*)(Pb_l + rb * AST + kc);
                    bl[nt][0] = t.x; bl[nt][1] = t.y;
                }
#pragma unroll
                for (int mt = 0; mt < 2; ++mt)
#pragma unroll
                    for (int nt = 0; nt < 4; ++nt)
                        mma16816(acc[mt][nh * 4 + nt], af[0][mt], bh[nt]);
#pragma unroll
                for (int mt = 0; mt < 2; ++mt)
#pragma unroll
                    for (int nt = 0; nt < 4; ++nt)
                        mma16816(acc[mt][nh * 4 + nt], af[0][mt], bl[nt]);
#pragma unroll
                for (int mt = 0; mt < 2; ++mt)
#pragma unroll
                    for (int nt = 0; nt < 4; ++nt)
                        mma16816(acc[mt][nh * 4 + nt], af[1][mt], bh[nt]);
            }
        }
        __syncthreads();
    }

    // epilogue
#pragma unroll
    for (int mt = 0; mt < 2; ++mt)
#pragma unroll
        for (int half = 0; half < 2; ++half) {
            const int m = m0 + wm * 32 + mt * 16 + g + half * 8;
            if (m >= M) continue;
#pragma unroll
            for (int ntg = 0; ntg < 8; ++ntg) {
                const int n = n0 + wn * 64 + ntg * 8 + 2 * c4;
                if (n >= N) continue;
                float2 o;
                o.x = acc[mt][ntg][half * 2 + 0] * alpha;
                o.y = acc[mt][ntg][half * 2 + 1] * alpha;
                if (bias) { o.x += bias[n]; o.y += bias[n + 1]; }
                const long off = (long)m * N + n;
                if (accum) {
                    float2 old = *(const float2*)(C + off);
                    o.x += old.x; o.y += old.y;
                }
                *(float2*)(C + off) = o;
                if (Chi) {
                    uint32_t h, l;
                    pack_split(o.x, o.y, h, l);
                    const int jj = n >> 1, jl = jj & 7;
                    const long so = (long)m * (N >> 1) + (jj & ~7) + KPERM(jl);
                    Chi[so] = h; Clo[so] = l;
                }
            }
        }
}

// ---------------------------------------------------------------------------
// transpose_split: fp32 h[b][l][d] -> split-perm h^T planes [b][d][l/2 u32]
// ---------------------------------------------------------------------------
__global__ __launch_bounds__(256) void transpose_split(
    const float* __restrict__ in, uint32_t* __restrict__ outh,
    uint32_t* __restrict__ outl, int L)
{
    __shared__ float t[32][33];
    const int b = blockIdx.z;
    const int l0 = blockIdx.x * 32;
    const int d0 = blockIdx.y * 32;
    in += (long)b * L * DM;
    const long obase = (long)b * DM * (L >> 1);
    const int tx = threadIdx.x & 31;
    const int ty = threadIdx.x >> 5;
#pragma unroll
    for (int i = ty; i < 32; i += 8)
        t[i][tx] = in[(long)(l0 + i) * DM + d0 + tx];
    __syncthreads();
#pragma unroll
    for (int q = 0; q < 2; ++q) {
        const int u = q * 256 + threadIdx.x;
        const int dl = u >> 4, pr = u & 15;
        float v0 = t[2 * pr][dl], v1 = t[2 * pr + 1][dl];
        uint32_t h, l;
        pack_split(v0, v1, h, l);
        const int jj = (l0 >> 1) + pr, jl = jj & 7;
        const long so = obase + (long)(d0 + dl) * (L >> 1) + (jj & ~7) + KPERM(jl);
        outh[so] = h; outl[so] = l;
    }
}

// ---------------------------------------------------------------------------
// Row softmax (p12): reads fp32 S, writes split-perm P12 planes. S untouched.
// allowed = (j < c2) || (i >= c1 && i-c1 >= j-c2)
// ---------------------------------------------------------------------------
template <int L2>
__global__ __launch_bounds__(256) void softmax12(
    const float* __restrict__ S, const float* __restrict__ mk,
    uint32_t* __restrict__ Phi, uint32_t* __restrict__ Plo, int L1, int c1, int c2)
{
    constexpr int NU = L2 / 64;
    const int warp = threadIdx.x >> 5;
    const int lane = threadIdx.x & 31;
    const int b = blockIdx.y;
    const int i = blockIdx.x * 8 + warp;
    if (i >= L1) return;
    const float* row = S + ((long)b * L1 + i) * L2;
    const float* m2 = mk + (long)b * L2;

    float v[2 * NU];
    float mx = -INFINITY;
#pragma unroll
    for (int t = 0; t < NU; ++t) {
        const int jj = t * 32 + lane;
        const int j = 2 * jj;
        float2 sv = *(const float2*)(row + j);
        float2 mm = *(const float2*)(m2 + j);
        float al0 = ((j < c2) || (i >= c1 && (i - c1) >= (j - c2))) ? 1.f : 0.f;
        float al1 = ((j + 1 < c2) || (i >= c1 && (i - c1) >= (j + 1 - c2))) ? 1.f : 0.f;
        v[2 * t + 0] = sv.x + (1.f - al0 * mm.x) * -10000.f;
        v[2 * t + 1] = sv.y + (1.f - al1 * mm.y) * -10000.f;
        mx = fmaxf(mx, fmaxf(v[2 * t], v[2 * t + 1]));
    }
#pragma unroll
    for (int off = 16; off > 0; off >>= 1)
        mx = fmaxf(mx, __shfl_xor_sync(0xffffffffu, mx, off));
    float Z = 0.f;
#pragma unroll
    for (int t = 0; t < 2 * NU; ++t) { v[t] = __expf(v[t] - mx); Z += v[t]; }
#pragma unroll
    for (int off = 16; off > 0; off >>= 1)
        Z += __shfl_xor_sync(0xffffffffu, Z, off);
    const float inv = 1.f / Z;
    const long base = ((long)b * L1 + i) * (L2 >> 1);
#pragma unroll
    for (int t = 0; t < NU; ++t) {
        const int jj = t * 32 + lane, jl = jj & 7;
        uint32_t h, l;
        pack_split(v[2 * t] * inv, v[2 * t + 1] * inv, h, l);
        const long so = base + (jj & ~7) + KPERM(jl);
        Phi[so] = h; Plo[so] = l;
    }
}

// ---------------------------------------------------------------------------
// Column softmax (p21): two-pass, small static smem (high occupancy).
// P21[b,j,i] = softmax_i(S[b,i,j] + bias21), split-perm planes (rows j, k=i).
// allowed = (i < c1) || (j >= c2 && j-c2 >= i-c1)
// ---------------------------------------------------------------------------
__global__ __launch_bounds__(256) void softmax21(
    const float* __restrict__ S, const float* __restrict__ mk1,
    uint32_t* __restrict__ Phi, uint32_t* __restrict__ Plo,
    int L1, int L2, int c1, int c2)
{
    const int tx = threadIdx.x & 31;
    const int ty = threadIdx.x >> 5;
    const int b = blockIdx.y;
    const int j0 = blockIdx.x * 32;
    const int j = j0 + tx;
    const float* Sb = S + (long)b * L1 * L2;
    const float* m1 = mk1 + (long)b * L1;

    float mx = -INFINITY, Z = 0.f;
    for (int i = ty; i < L1; i += 8) {
        float allowed = ((i < c1) || (j >= c2 && (j - c2) >= (i - c1))) ? 1.f : 0.f;
        float s = Sb[(long)i * L2 + j] + (1.f - allowed * m1[i]) * -10000.f;
        if (s > mx) { Z = Z * __expf(mx - s) + 1.f; mx = s; }
        else        { Z += __expf(s - mx); }
    }
    __shared__ float smx[8][32];
    __shared__ float ssum[8][32];
    smx[ty][tx] = mx; ssum[ty][tx] = Z;
    __syncthreads();
    if (ty == 0) {
        float m = smx[0][tx], z = ssum[0][tx];
#pragma unroll
        for (int r = 1; r < 8; ++r) {
            float m2 = smx[r][tx], z2 = ssum[r][tx];
            float mm = fmaxf(m, m2);
            z = z * __expf(m - mm) + z2 * __expf(m2 - mm);
            m = mm;
        }
        smx[0][tx] = m; ssum[0][tx] = 1.f / z;
    }
    __syncthreads();
    const float rowmax = smx[0][tx];
    const float invZ = ssum[0][tx];

    __shared__ float tile[32][33];
    for (int i0 = 0; i0 < L1; i0 += 32) {
#pragma unroll
        for (int ii = ty; ii < 32; ii += 8) {
            const int i = i0 + ii;
            float allowed = ((i < c1) || (j >= c2 && (j - c2) >= (i - c1))) ? 1.f : 0.f;
            float s = Sb[(long)i * L2 + j] + (1.f - allowed * m1[i]) * -10000.f;
            tile[tx][ii] = __expf(s - rowmax) * invZ;
        }
        __syncthreads();
#pragma unroll
        for (int q = 0; q < 2; ++q) {
            const int u = q * 256 + threadIdx.x;
            const int jl2 = u >> 4, pr = u & 15;
            uint32_t h, l;
            pack_split(tile[jl2][2 * pr], tile[jl2][2 * pr + 1], h, l);
            const int jj = (i0 >> 1) + pr, jg = jj & 7;
            const long so = ((long)b * L2 + j0 + jl2) * (L1 >> 1) + (jj & ~7) + KPERM(jg);
            Phi[so] = h; Plo[so] = l;
        }
        __syncthreads();
    }
}

// ---------------------------------------------------------------------------
static inline dim3 gg(int M, int N, int batch) {
    return dim3((unsigned)((N + BN - 1) / BN), (unsigned)((M + BM - 1) / BM), (unsigned)batch);
}

extern "C" void kernel_launch(void* const* d_in, const int* in_sizes, int n_in,
                              void* d_out, int out_size)
{
    const float* vemb = (const float*)d_in[0];
    const float* mv   = (const float*)d_in[1];
    const float* demb = (const float*)d_in[2];
    const float* md   = (const float*)d_in[3];
    const float* aemb = (const float*)d_in[4];
    const float* ma   = (const float*)d_in[5];
    const float* Wv   = (const float*)d_in[6];
    const float* bv   = (const float*)d_in[7];
    const float* Wd   = (const float*)d_in[8];
    const float* bd   = (const float*)d_in[9];
    const float* Wa   = (const float*)d_in[10];
    const float* ba   = (const float*)d_in[11];

    float* out1 = (float*)d_out;
    float* out2 = out1 + (size_t)NB * LV * DM;
    float* out3 = out2 + (size_t)NB * LD * DM;

#define GA(v, s) cudaGetSymbolAddress((void**)&v, s)
    float *vid, *det, *act, *S;
    uint32_t *xvh, *xvl, *xdh, *xdl, *xah, *xal;
    uint32_t *wvh, *wvl, *wdh, *wdl, *wah, *wal;
    uint32_t *vh, *vl, *dh, *dl, *ah, *al;
    uint32_t *vTh, *vTl, *dTh, *dTl, *aTh, *aTl;
    uint32_t *p12h, *p12l, *p21h, *p21l;
    GA(vid, g_vid); GA(det, g_det); GA(act, g_act); GA(S, g_S);
    GA(xvh, g_xvh); GA(xvl, g_xvl); GA(xdh, g_xdh); GA(xdl, g_xdl);
    GA(xah, g_xah); GA(xal, g_xal);
    GA(wvh, g_wvh); GA(wvl, g_wvl); GA(wdh, g_wdh); GA(wdl, g_wdl);
    GA(wah, g_wah); GA(wal, g_wal);
    GA(vh, g_vh); GA(vl, g_vl); GA(dh, g_dh); GA(dl, g_dl);
    GA(ah, g_ah); GA(al, g_al);
    GA(vTh, g_vTh); GA(vTl, g_vTl); GA(dTh, g_dTh); GA(dTl, g_dTl);
    GA(aTh, g_aTh); GA(aTl, g_aTl);
    GA(p12h, g_p12h); GA(p12l, g_p12l); GA(p21h, g_p21h); GA(p21l, g_p21l);
#undef GA

    cudaFuncSetAttribute(gemm_split, cudaFuncAttributeMaxDynamicSharedMemorySize, GEMM_SMEM);

    // ---- split source inputs (X and W) ----
    {
        long tv = (long)NB * LV * (DM / 16), td = (long)NB * LD * (DM / 16),
             ta = (long)NB * LA * (DM / 16), tw = (long)DM * (DM / 16);
        split_src<<<(unsigned)((tv + 255) / 256), 256>>>(vemb, xvh, xvl, tv, DM);
        split_src<<<(unsigned)((td + 255) / 256), 256>>>(demb, xdh, xdl, td, DM);
        split_src<<<(unsigned)((ta + 255) / 256), 256>>>(aemb, xah, xal, ta, DM);
        split_src<<<(unsigned)((tw + 255) / 256), 256>>>(Wv, wvh, wvl, tw, DM);
        split_src<<<(unsigned)((tw + 255) / 256), 256>>>(Wd, wdh, wdl, tw, DM);
        split_src<<<(unsigned)((tw + 255) / 256), 256>>>(Wa, wah, wal, tw, DM);
    }

    // ---- projections: h = X @ W^T + b  (writes fp32 h + split h) ----
    gemm_split<<<gg(NB * LV, DM, 1), 256, GEMM_SMEM>>>(xvh, xvl, wvh, wvl, bv, vid,
        vh, vl, NB * LV, DM, DM, 0, 0, 0, 1.f, 0);
    gemm_split<<<gg(NB * LD, DM, 1), 256, GEMM_SMEM>>>(xdh, xdl, wdh, wdl, bd, det,
        dh, dl, NB * LD, DM, DM, 0, 0, 0, 1.f, 0);
    gemm_split<<<gg(NB * LA, DM, 1), 256, GEMM_SMEM>>>(xah, xal, wah, wal, ba, act,
        ah, al, NB * LA, DM, DM, 0, 0, 0, 1.f, 0);

    // ---- transposed split copies for PV GEMMs ----
    transpose_split<<<dim3(LV / 32, DM / 32, NB), 256>>>(vid, vTh, vTl, LV);
    transpose_split<<<dim3(LD / 32, DM / 32, NB), 256>>>(det, dTh, dTl, LD);
    transpose_split<<<dim3(LA / 32, DM / 32, NB), 256>>>(act, aTh, aTl, LA);

    // ==== pair A: vid (L1=576, c1=512) x det (L2=320, c2=256) ====
    gemm_split<<<gg(LV, LD, NB), 256, GEMM_SMEM>>>(vh, vl, dh, dl, nullptr, S,
        nullptr, nullptr, LV, LD, DM,
        (long)LV * (DM / 2), (long)LD * (DM / 2), (long)LV * LD, 0.125f, 0);
    softmax21<<<dim3(LD / 32, NB), 256>>>(S, mv, p21h, p21l, LV, LD, CV, CD);
    softmax12<LD><<<dim3(LV / 8, NB), 256>>>(S, md, p12h, p12l, LV, CV, CD);
    gemm_split<<<gg(LV, DM, NB), 256, GEMM_SMEM>>>(p12h, p12l, dTh, dTl, nullptr, out1,
        nullptr, nullptr, LV, DM, LD,
        (long)LV * (LD / 2), (long)DM * (LD / 2), (long)LV * DM, 1.f, 0);   // c_vd
    gemm_split<<<gg(LD, DM, NB), 256, GEMM_SMEM>>>(p21h, p21l, vTh, vTl, nullptr, out2,
        nullptr, nullptr, LD, DM, LV,
        (long)LD * (LV / 2), (long)DM * (LV / 2), (long)LD * DM, 1.f, 0);   // c_dv

    // ==== pair B: vid (576, 512) x act (192, 128) ====
    gemm_split<<<gg(LV, LA, NB), 256, GEMM_SMEM>>>(vh, vl, ah, al, nullptr, S,
        nullptr, nullptr, LV, LA, DM,
        (long)LV * (DM / 2), (long)LA * (DM / 2), (long)LV * LA, 0.125f, 0);
    softmax21<<<dim3(LA / 32, NB), 256>>>(S, mv, p21h, p21l, LV, LA, CV, CA);
    softmax12<LA><<<dim3(LV / 8, NB), 256>>>(S, ma, p12h, p12l, LV, CV, CA);
    gemm_split<<<gg(LV, DM, NB), 256, GEMM_SMEM>>>(p12h, p12l, aTh, aTl, nullptr, out1,
        nullptr, nullptr, LV, DM, LA,
        (long)LV * (LA / 2), (long)DM * (LA / 2), (long)LV * DM, 1.f, 1);   // += c_va
    gemm_split<<<gg(LA, DM, NB), 256, GEMM_SMEM>>>(p21h, p21l, vTh, vTl, nullptr, out3,
        nullptr, nullptr, LA, DM, LV,
        (long)LA * (LV / 2), (long)DM * (LV / 2), (long)LA * DM, 1.f, 0);   // c_av

    // ==== pair C: act (192, 128) x det (320, 256) ====
    gemm_split<<<gg(LA, LD, NB), 256, GEMM_SMEM>>>(ah, al, dh, dl, nullptr, S,
        nullptr, nullptr, LA, LD, DM,
        (long)LA * (DM / 2), (long)LD * (DM / 2), (long)LA * LD, 0.125f, 0);
    softmax21<<<dim3(LD / 32, NB), 256>>>(S, ma, p21h, p21l, LA, LD, CA, CD);
    softmax12<LD><<<dim3(LA / 8, NB), 256>>>(S, md, p12h, p12l, LA, CA, CD);
    gemm_split<<<gg(LA, DM, NB), 256, GEMM_SMEM>>>(p12h, p12l, dTh, dTl, nullptr, out3,
        nullptr, nullptr, LA, DM, LD,
        (long)LA * (LD / 2), (long)DM * (LD / 2), (long)LA * DM, 1.f, 1);   // += c_ad
    gemm_split<<<gg(LD, DM, NB), 256, GEMM_SMEM>>>(p21h, p21l, aTh, aTl, nullptr, out2,
        nullptr, nullptr, LD, DM, LA,
        (long)LD * (LA / 2), (long)DM * (LA / 2), (long)LD * DM, 1.f, 1);   // += c_da
}

// round 8
// speedup vs baseline: 1.2507x; 1.1329x over previous
#include <cuda_runtime.h>
#include <cuda_bf16.h>
#include <cstdint>
#include <math.h>

#define NB 64
#define DM 768
#define LV 576
#define LD 320
#define LA 192
#define CV 512
#define CD 256
#define CA 128

// GEMM tile config
#define BM 128
#define BN 128
// AST=24: row base bank = (24*r)%32 cycles {0,24,16,8}; fragment LDS.64 over
// g=0..7 rows + kc offsets {0,2,4,6} covers all 32 banks exactly once per
// half-warp phase -> conflict-free fragment loads (hot path).
#define AST 24
#define PL  (128 * AST)
#define BUF (4 * PL)             // per stage (Ah, Al, Bh, Bl)
#define GEMM_SMEM (2 * BUF * 4)  // 98304 B

#define KPERM(jl) ((((jl) & 3) * 2) + ((jl) >> 2))

// ---------------- scratch (device globals; no runtime allocation) ----------
__device__ float g_vid[(size_t)NB * LV * DM];
__device__ float g_det[(size_t)NB * LD * DM];
__device__ float g_act[(size_t)NB * LA * DM];
__device__ uint32_t g_xvh[(size_t)NB * LV * (DM / 2)], g_xvl[(size_t)NB * LV * (DM / 2)];
__device__ uint32_t g_xdh[(size_t)NB * LD * (DM / 2)], g_xdl[(size_t)NB * LD * (DM / 2)];
__device__ uint32_t g_xah[(size_t)NB * LA * (DM / 2)], g_xal[(size_t)NB * LA * (DM / 2)];
__device__ uint32_t g_wvh[DM * (DM / 2)], g_wvl[DM * (DM / 2)];
__device__ uint32_t g_wdh[DM * (DM / 2)], g_wdl[DM * (DM / 2)];
__device__ uint32_t g_wah[DM * (DM / 2)], g_wal[DM * (DM / 2)];
__device__ uint32_t g_vh[(size_t)NB * LV * (DM / 2)], g_vl[(size_t)NB * LV * (DM / 2)];
__device__ uint32_t g_dh[(size_t)NB * LD * (DM / 2)], g_dl[(size_t)NB * LD * (DM / 2)];
__device__ uint32_t g_ah[(size_t)NB * LA * (DM / 2)], g_al[(size_t)NB * LA * (DM / 2)];
__device__ uint32_t g_vTh[(size_t)NB * DM * (LV / 2)], g_vTl[(size_t)NB * DM * (LV / 2)];
__device__ uint32_t g_dTh[(size_t)NB * DM * (LD / 2)], g_dTl[(size_t)NB * DM * (LD / 2)];
__device__ uint32_t g_aTh[(size_t)NB * DM * (LA / 2)], g_aTl[(size_t)NB * DM * (LA / 2)];
__device__ float    g_S  [(size_t)NB * LV * LD];
__device__ uint32_t g_p12h[(size_t)NB * LV * (LD / 2)], g_p12l[(size_t)NB * LV * (LD / 2)];
__device__ uint32_t g_p21h[(size_t)NB * LV * (LD / 2)], g_p21l[(size_t)NB * LV * (LD / 2)];

// ---------------- helpers ---------------------------------------------------
__device__ __forceinline__ uint32_t smem_u32(const void* p) {
    uint32_t a;
    asm("{ .reg .u64 t; cvta.to.shared.u64 t, %1; cvt.u32.u64 %0, t; }" : "=r"(a) : "l"(p));
    return a;
}

__device__ __forceinline__ void mma16816(float* d, const uint32_t* a, const uint32_t* b)
{
    asm volatile(
        "mma.sync.aligned.m16n8k16.row.col.f32.bf16.bf16.f32 "
        "{%0,%1,%2,%3}, {%4,%5,%6,%7}, {%8,%9}, {%0,%1,%2,%3};"
        : "+f"(d[0]), "+f"(d[1]), "+f"(d[2]), "+f"(d[3])
        : "r"(a[0]), "r"(a[1]), "r"(a[2]), "r"(a[3]), "r"(b[0]), "r"(b[1]));
}

__device__ __forceinline__ void pack_split(float x, float y, uint32_t& hi, uint32_t& lo)
{
    __nv_bfloat162 h = __floats2bfloat162_rn(x, y);
    float hx = __bfloat162float(__low2bfloat16(h));
    float hy = __bfloat162float(__high2bfloat16(h));
    __nv_bfloat162 l = __floats2bfloat162_rn(x - hx, y - hy);
    hi = *reinterpret_cast<uint32_t*>(&h);
    lo = *reinterpret_cast<uint32_t*>(&l);
}

// ---------------------------------------------------------------------------
// split_src: fp32 row-major [rows, Kf] -> hi/lo bf16x2 planes, pre-permuted.
// ---------------------------------------------------------------------------
__global__ __launch_bounds__(256) void split_src(
    const float* __restrict__ in, uint32_t* __restrict__ hi, uint32_t* __restrict__ lo,
    long total, int Kf)
{
    long u = (long)blockIdx.x * 256 + threadIdx.x;
    if (u >= total) return;
    const int gpr = Kf >> 4;
    long row = u / gpr;
    int grp = (int)(u - row * gpr);
    const float* p = in + row * (long)Kf + grp * 16;
    float f[16];
#pragma unroll
    for (int q = 0; q < 4; ++q) *(float4*)(f + q * 4) = *(const float4*)(p + q * 4);
    uint32_t h[8], l[8];
#pragma unroll
    for (int j = 0; j < 8; ++j) pack_split(f[2 * j], f[2 * j + 1], h[j], l[j]);
    uint32_t* dh = hi + row * (long)(Kf >> 1) + grp * 8;
    uint32_t* dl = lo + row * (long)(Kf >> 1) + grp * 8;
    *(uint4*)(dh + 0) = make_uint4(h[0], h[4], h[1], h[5]);
    *(uint4*)(dh + 4) = make_uint4(h[2], h[6], h[3], h[7]);
    *(uint4*)(dl + 0) = make_uint4(l[0], l[4], l[1], l[5]);
    *(uint4*)(dl + 4) = make_uint4(l[2], l[6], l[3], l[7]);
}

// ---------------------------------------------------------------------------
// gemm_split: NT GEMM on pre-split pre-permuted bf16 planes.
// C[b,m,n] = alpha*sum_k A[m,k]*B[n,k] (+bias) (+=C); optional split-out.
// ---------------------------------------------------------------------------
__global__ __launch_bounds__(256, 2) void gemm_split(
    const uint32_t* __restrict__ Ah, const uint32_t* __restrict__ Al,
    const uint32_t* __restrict__ Bh, const uint32_t* __restrict__ Bl,
    const float* __restrict__ bias, float* __restrict__ C,
    uint32_t* __restrict__ Chi, uint32_t* __restrict__ Clo,
    int M, int N, int K, long sA, long sB, long sC, float alpha, int accum)
{
    extern __shared__ uint32_t sm[];
    const int tid = threadIdx.x;
    const int bz = blockIdx.z;
    Ah += (long)bz * sA; Al += (long)bz * sA;
    Bh += (long)bz * sB; Bl += (long)bz * sB;
    C  += (long)bz * sC;

    const int m0 = blockIdx.y * BM;
    const int n0 = blockIdx.x * BN;
    const int K2 = K >> 1;
    const int nc = K >> 5;

    const int wid = tid >> 5, lane = tid & 31;
    const int wm = wid >> 1, wn = wid & 1;
    const int g = lane >> 2, c4 = lane & 3;

    const uint32_t smem_base = smem_u32(sm);

    float acc[2][8][4];
#pragma unroll
    for (int mt = 0; mt < 2; ++mt)
#pragma unroll
        for (int nt = 0; nt < 8; ++nt)
#pragma unroll
            for (int q = 0; q < 4; ++q) acc[mt][nt][q] = 0.f;

    auto issue = [&](int cc, int buf) {
#pragma unroll
        for (int it = 0; it < 8; ++it) {
            const int plane = it >> 1;
            const int u = ((it & 1) << 8) + tid;
            const int row = u >> 2, ch = u & 3;
            uint32_t dst = smem_base +
                (uint32_t)((buf * BUF + plane * PL + row * AST + ch * 4) * 4);
            const uint32_t* srcb;
            bool valid;
            if (plane < 2) {
                valid = (m0 + row) < M;
                srcb = (plane == 0 ? Ah : Al) + (long)(valid ? m0 + row : 0) * K2 + cc * 16 + ch * 4;
            } else {
                valid = (n0 + row) < N;
                srcb = (plane == 2 ? Bh : Bl) + (long)(valid ? n0 + row : 0) * K2 + cc * 16 + ch * 4;
            }
            int sb = valid ? 16 : 0;
            asm volatile("cp.async.cg.shared.global [%0], [%1], 16, %2;"
                         :: "r"(dst), "l"(srcb), "r"(sb) : "memory");
        }
        asm volatile("cp.async.commit_group;" ::: "memory");
    };

    issue(0, 0);

    for (int c = 0; c < nc; ++c) {
        if (c + 1 < nc) {
            issue(c + 1, (c + 1) & 1);
            asm volatile("cp.async.wait_group 1;" ::: "memory");
        } else {
            asm volatile("cp.async.wait_group 0;" ::: "memory");
        }
        __syncthreads();

        const uint32_t* Pa_h = sm + (c & 1) * BUF;
        const uint32_t* Pa_l = Pa_h + PL;
        const uint32_t* Pb_h = Pa_h + 2 * PL;
        const uint32_t* Pb_l = Pa_h + 3 * PL;

#pragma unroll
        for (int s = 0; s < 2; ++s) {
            const int kc = s * 8 + 2 * c4;
            uint32_t af[2][2][4];
#pragma unroll
            for (int mt = 0; mt < 2; ++mt) {
                const int r = wm * 32 + mt * 16 + g;
                uint2 t0 = *(const uint2*)(Pa_h + r * AST + kc);
                uint2 t1 = *(const uint2*)(Pa_h + (r + 8) * AST + kc);
                af[0][mt][0] = t0.x; af[0][mt][1] = t1.x;
                af[0][mt][2] = t0.y; af[0][mt][3] = t1.y;
                t0 = *(const uint2*)(Pa_l + r * AST + kc);
                t1 = *(const uint2*)(Pa_l + (r + 8) * AST + kc);
                af[1][mt][0] = t0.x; af[1][mt][1] = t1.x;
                af[1][mt][2] = t0.y; af[1][mt][3] = t1.y;
            }
#pragma unroll
            for (int nh = 0; nh < 2; ++nh) {
                uint32_t bh[4][2], bl[4][2];
#pragma unroll
                for (int nt = 0; nt < 4; ++nt) {
                    const int rb = wn * 64 + nh * 32 + nt * 8 + g;
                    uint2 t = *(const uint2*)(Pb_h + rb * AST + kc);
                    bh[nt][0] = t.x; bh[nt][1] = t.y;
                    t = *(const uint2*)(Pb_l + rb * AST + kc);
                    bl[nt][0] = t.x; bl[nt][1] = t.y;
                }
#pragma unroll
                for (int mt = 0; mt < 2; ++mt)
#pragma unroll
                    for (int nt = 0; nt < 4; ++nt)
                        mma16816(acc[mt][nh * 4 + nt], af[0][mt], bh[nt]);
#pragma unroll
                for (int mt = 0; mt < 2; ++mt)
#pragma unroll
                    for (int nt = 0; nt < 4; ++nt)
                        mma16816(acc[mt][nh * 4 + nt], af[0][mt], bl[nt]);
#pragma unroll
                for (int mt = 0; mt < 2; ++mt)
#pragma unroll
                    for (int nt = 0; nt < 4; ++nt)
                        mma16816(acc[mt][nh * 4 + nt], af[1][mt], bh[nt]);
            }
        }
        __syncthreads();
    }

    // epilogue
#pragma unroll
    for (int mt = 0; mt < 2; ++mt)
#pragma unroll
        for (int half = 0; half < 2; ++half) {
            const int m = m0 + wm * 32 + mt * 16 + g + half * 8;
            if (m >= M) continue;
#pragma unroll
            for (int ntg = 0; ntg < 8; ++ntg) {
                const int n = n0 + wn * 64 + ntg * 8 + 2 * c4;
                if (n >= N) continue;
                float2 o;
                o.x = acc[mt][ntg][half * 2 + 0] * alpha;
                o.y = acc[mt][ntg][half * 2 + 1] * alpha;
                if (bias) { o.x += bias[n]; o.y += bias[n + 1]; }
                const long off = (long)m * N + n;
                if (accum) {
                    float2 old = *(const float2*)(C + off);
                    o.x += old.x; o.y += old.y;
                }
                *(float2*)(C + off) = o;
                if (Chi) {
                    uint32_t h, l;
                    pack_split(o.x, o.y, h, l);
                    const int jj = n >> 1, jl = jj & 7;
                    const long so = (long)m * (N >> 1) + (jj & ~7) + KPERM(jl);
                    Chi[so] = h; Clo[so] = l;
                }
            }
        }
}

// ---------------------------------------------------------------------------
// transpose_split: fp32 h[b][l][d] -> split-perm h^T planes [b][d][l/2 u32]
// ---------------------------------------------------------------------------
__global__ __launch_bounds__(256) void transpose_split(
    const float* __restrict__ in, uint32_t* __restrict__ outh,
    uint32_t* __restrict__ outl, int L)
{
    __shared__ float t[32][33];
    const int b = blockIdx.z;
    const int l0 = blockIdx.x * 32;
    const int d0 = blockIdx.y * 32;
    in += (long)b * L * DM;
    const long obase = (long)b * DM * (L >> 1);
    const int tx = threadIdx.x & 31;
    const int ty = threadIdx.x >> 5;
#pragma unroll
    for (int i = ty; i < 32; i += 8)
        t[i][tx] = in[(long)(l0 + i) * DM + d0 + tx];
    __syncthreads();
#pragma unroll
    for (int q = 0; q < 2; ++q) {
        const int u = q * 256 + threadIdx.x;
        const int dl = u >> 4, pr = u & 15;
        float v0 = t[2 * pr][dl], v1 = t[2 * pr + 1][dl];
        uint32_t h, l;
        pack_split(v0, v1, h, l);
        const int jj = (l0 >> 1) + pr, jl = jj & 7;
        const long so = obase + (long)(d0 + dl) * (L >> 1) + (jj & ~7) + KPERM(jl);
        outh[so] = h; outl[so] = l;
    }
}

// ---------------------------------------------------------------------------
// Row softmax (p12): reads fp32 S, writes split-perm P12 planes. S untouched.
// allowed = (j < c2) || (i >= c1 && i-c1 >= j-c2)
// ---------------------------------------------------------------------------
template <int L2>
__global__ __launch_bounds__(256) void softmax12(
    const float* __restrict__ S, const float* __restrict__ mk,
    uint32_t* __restrict__ Phi, uint32_t* __restrict__ Plo, int L1, int c1, int c2)
{
    constexpr int NU = L2 / 64;
    const int warp = threadIdx.x >> 5;
    const int lane = threadIdx.x & 31;
    const int b = blockIdx.y;
    const int i = blockIdx.x * 8 + warp;
    if (i >= L1) return;
    const float* row = S + ((long)b * L1 + i) * L2;
    const float* m2 = mk + (long)b * L2;

    float v[2 * NU];
    float mx = -INFINITY;
#pragma unroll
    for (int t = 0; t < NU; ++t) {
        const int jj = t * 32 + lane;
        const int j = 2 * jj;
        float2 sv = *(const float2*)(row + j);
        float2 mm = *(const float2*)(m2 + j);
        float al0 = ((j < c2) || (i >= c1 && (i - c1) >= (j - c2))) ? 1.f : 0.f;
        float al1 = ((j + 1 < c2) || (i >= c1 && (i - c1) >= (j + 1 - c2))) ? 1.f : 0.f;
        v[2 * t + 0] = sv.x + (1.f - al0 * mm.x) * -10000.f;
        v[2 * t + 1] = sv.y + (1.f - al1 * mm.y) * -10000.f;
        mx = fmaxf(mx, fmaxf(v[2 * t], v[2 * t + 1]));
    }
#pragma unroll
    for (int off = 16; off > 0; off >>= 1)
        mx = fmaxf(mx, __shfl_xor_sync(0xffffffffu, mx, off));
    float Z = 0.f;
#pragma unroll
    for (int t = 0; t < 2 * NU; ++t) { v[t] = __expf(v[t] - mx); Z += v[t]; }
#pragma unroll
    for (int off = 16; off > 0; off >>= 1)
        Z += __shfl_xor_sync(0xffffffffu, Z, off);
    const float inv = 1.f / Z;
    const long base = ((long)b * L1 + i) * (L2 >> 1);
#pragma unroll
    for (int t = 0; t < NU; ++t) {
        const int jj = t * 32 + lane, jl = jj & 7;
        uint32_t h, l;
        pack_split(v[2 * t] * inv, v[2 * t + 1] * inv, h, l);
        const long so = base + (jj & ~7) + KPERM(jl);
        Phi[so] = h; Plo[so] = l;
    }
}

// ---------------------------------------------------------------------------
// Column softmax (p21): two-pass, small static smem (high occupancy).
// P21[b,j,i] = softmax_i(S[b,i,j] + bias21), split-perm planes (rows j, k=i).
// allowed = (i < c1) || (j >= c2 && j-c2 >= i-c1)
// ---------------------------------------------------------------------------
__global__ __launch_bounds__(256) void softmax21(
    const float* __restrict__ S, const float* __restrict__ mk1,
    uint32_t* __restrict__ Phi, uint32_t* __restrict__ Plo,
    int L1, int L2, int c1, int c2)
{
    const int tx = threadIdx.x & 31;
    const int ty = threadIdx.x >> 5;
    const int b = blockIdx.y;
    const int j0 = blockIdx.x * 32;
    const int j = j0 + tx;
    const float* Sb = S + (long)b * L1 * L2;
    const float* m1 = mk1 + (long)b * L1;

    float mx = -INFINITY, Z = 0.f;
    for (int i = ty; i < L1; i += 8) {
        float allowed = ((i < c1) || (j >= c2 && (j - c2) >= (i - c1))) ? 1.f : 0.f;
        float s = Sb[(long)i * L2 + j] + (1.f - allowed * m1[i]) * -10000.f;
        if (s > mx) { Z = Z * __expf(mx - s) + 1.f; mx = s; }
        else        { Z += __expf(s - mx); }
    }
    __shared__ float smx[8][32];
    __shared__ float ssum[8][32];
    smx[ty][tx] = mx; ssum[ty][tx] = Z;
    __syncthreads();
    if (ty == 0) {
        float m = smx[0][tx], z = ssum[0][tx];
#pragma unroll
        for (int r = 1; r < 8; ++r) {
            float m2 = smx[r][tx], z2 = ssum[r][tx];
            float mm = fmaxf(m, m2);
            z = z * __expf(m - mm) + z2 * __expf(m2 - mm);
            m = mm;
        }
        smx[0][tx] = m; ssum[0][tx] = 1.f / z;
    }
    __syncthreads();
    const float rowmax = smx[0][tx];
    const float invZ = ssum[0][tx];

    __shared__ float tile[32][33];
    for (int i0 = 0; i0 < L1; i0 += 32) {
#pragma unroll
        for (int ii = ty; ii < 32; ii += 8) {
            const int i = i0 + ii;
            float allowed = ((i < c1) || (j >= c2 && (j - c2) >= (i - c1))) ? 1.f : 0.f;
            float s = Sb[(long)i * L2 + j] + (1.f - allowed * m1[i]) * -10000.f;
            tile[tx][ii] = __expf(s - rowmax) * invZ;
        }
        __syncthreads();
#pragma unroll
        for (int q = 0; q < 2; ++q) {
            const int u = q * 256 + threadIdx.x;
            const int jl2 = u >> 4, pr = u & 15;
            uint32_t h, l;
            pack_split(tile[jl2][2 * pr], tile[jl2][2 * pr + 1], h, l);
            const int jj = (i0 >> 1) + pr, jg = jj & 7;
            const long so = ((long)b * L2 + j0 + jl2) * (L1 >> 1) + (jj & ~7) + KPERM(jg);
            Phi[so] = h; Plo[so] = l;
        }
        __syncthreads();
    }
}

// ---------------------------------------------------------------------------
static inline dim3 gg(int M, int N, int batch) {
    return dim3((unsigned)((N + BN - 1) / BN), (unsigned)((M + BM - 1) / BM), (unsigned)batch);
}

extern "C" void kernel_launch(void* const* d_in, const int* in_sizes, int n_in,
                              void* d_out, int out_size)
{
    const float* vemb = (const float*)d_in[0];
    const float* mv   = (const float*)d_in[1];
    const float* demb = (const float*)d_in[2];
    const float* md   = (const float*)d_in[3];
    const float* aemb = (const float*)d_in[4];
    const float* ma   = (const float*)d_in[5];
    const float* Wv   = (const float*)d_in[6];
    const float* bv   = (const float*)d_in[7];
    const float* Wd   = (const float*)d_in[8];
    const float* bd   = (const float*)d_in[9];
    const float* Wa   = (const float*)d_in[10];
    const float* ba   = (const float*)d_in[11];

    float* out1 = (float*)d_out;
    float* out2 = out1 + (size_t)NB * LV * DM;
    float* out3 = out2 + (size_t)NB * LD * DM;

#define GA(v, s) cudaGetSymbolAddress((void**)&v, s)
    float *vid, *det, *act, *S;
    uint32_t *xvh, *xvl, *xdh, *xdl, *xah, *xal;
    uint32_t *wvh, *wvl, *wdh, *wdl, *wah, *wal;
    uint32_t *vh, *vl, *dh, *dl, *ah, *al;
    uint32_t *vTh, *vTl, *dTh, *dTl, *aTh, *aTl;
    uint32_t *p12h, *p12l, *p21h, *p21l;
    GA(vid, g_vid); GA(det, g_det); GA(act, g_act); GA(S, g_S);
    GA(xvh, g_xvh); GA(xvl, g_xvl); GA(xdh, g_xdh); GA(xdl, g_xdl);
    GA(xah, g_xah); GA(xal, g_xal);
    GA(wvh, g_wvh); GA(wvl, g_wvl); GA(wdh, g_wdh); GA(wdl, g_wdl);
    GA(wah, g_wah); GA(wal, g_wal);
    GA(vh, g_vh); GA(vl, g_vl); GA(dh, g_dh); GA(dl, g_dl);
    GA(ah, g_ah); GA(al, g_al);
    GA(vTh, g_vTh); GA(vTl, g_vTl); GA(dTh, g_dTh); GA(dTl, g_dTl);
    GA(aTh, g_aTh); GA(aTl, g_aTl);
    GA(p12h, g_p12h); GA(p12l, g_p12l); GA(p21h, g_p21h); GA(p21l, g_p21l);
#undef GA

    cudaFuncSetAttribute(gemm_split, cudaFuncAttributeMaxDynamicSharedMemorySize, GEMM_SMEM);

    const long tv = (long)NB * LV * (DM / 16), td = (long)NB * LD * (DM / 16),
               ta = (long)NB * LA * (DM / 16), tw = (long)DM * (DM / 16);

    // ---- order chosen so launch index 3 (the one ncu captures) = proj GEMM ----
    split_src<<<(unsigned)((tw + 255) / 256), 256>>>(Wv, wvh, wvl, tw, DM);     // 0
    split_src<<<(unsigned)((tv + 255) / 256), 256>>>(vemb, xvh, xvl, tv, DM);   // 1
    split_src<<<(unsigned)((tw + 255) / 256), 256>>>(Wd, wdh, wdl, tw, DM);     // 2
    // 3: captured by ncu
    gemm_split<<<gg(NB * LV, DM, 1), 256, GEMM_SMEM>>>(xvh, xvl, wvh, wvl, bv, vid,
        vh, vl, NB * LV, DM, DM, 0, 0, 0, 1.f, 0);
    split_src<<<(unsigned)((td + 255) / 256), 256>>>(demb, xdh, xdl, td, DM);   // 4
    split_src<<<(unsigned)((ta + 255) / 256), 256>>>(aemb, xah, xal, ta, DM);   // 5
    split_src<<<(unsigned)((tw + 255) / 256), 256>>>(Wa, wah, wal, tw, DM);     // 6

    gemm_split<<<gg(NB * LD, DM, 1), 256, GEMM_SMEM>>>(xdh, xdl, wdh, wdl, bd, det,
        dh, dl, NB * LD, DM, DM, 0, 0, 0, 1.f, 0);
    gemm_split<<<gg(NB * LA, DM, 1), 256, GEMM_SMEM>>>(xah, xal, wah, wal, ba, act,
        ah, al, NB * LA, DM, DM, 0, 0, 0, 1.f, 0);

    // ---- transposed split copies for PV GEMMs ----
    transpose_split<<<dim3(LV / 32, DM / 32, NB), 256>>>(vid, vTh, vTl, LV);
    transpose_split<<<dim3(LD / 32, DM / 32, NB), 256>>>(det, dTh, dTl, LD);
    transpose_split<<<dim3(LA / 32, DM / 32, NB), 256>>>(act, aTh, aTl, LA);

    // ==== pair A: vid (L1=576, c1=512) x det (L2=320, c2=256) ====
    gemm_split<<<gg(LV, LD, NB), 256, GEMM_SMEM>>>(vh, vl, dh, dl, nullptr, S,
        nullptr, nullptr, LV, LD, DM,
        (long)LV * (DM / 2), (long)LD * (DM / 2), (long)LV * LD, 0.125f, 0);
    softmax21<<<dim3(LD / 32, NB), 256>>>(S, mv, p21h, p21l, LV, LD, CV, CD);
    softmax12<LD><<<dim3(LV / 8, NB), 256>>>(S, md, p12h, p12l, LV, CV, CD);
    gemm_split<<<gg(LV, DM, NB), 256, GEMM_SMEM>>>(p12h, p12l, dTh, dTl, nullptr, out1,
        nullptr, nullptr, LV, DM, LD,
        (long)LV * (LD / 2), (long)DM * (LD / 2), (long)LV * DM, 1.f, 0);   // c_vd
    gemm_split<<<gg(LD, DM, NB), 256, GEMM_SMEM>>>(p21h, p21l, vTh, vTl, nullptr, out2,
        nullptr, nullptr, LD, DM, LV,
        (long)LD * (LV / 2), (long)DM * (LV / 2), (long)LD * DM, 1.f, 0);   // c_dv

    // ==== pair B: vid (576, 512) x act (192, 128) ====
    gemm_split<<<gg(LV, LA, NB), 256, GEMM_SMEM>>>(vh, vl, ah, al, nullptr, S,
        nullptr, nullptr, LV, LA, DM,
        (long)LV * (DM / 2), (long)LA * (DM / 2), (long)LV * LA, 0.125f, 0);
    softmax21<<<dim3(LA / 32, NB), 256>>>(S, mv, p21h, p21l, LV, LA, CV, CA);
    softmax12<LA><<<dim3(LV / 8, NB), 256>>>(S, ma, p12h, p12l, LV, CV, CA);
    gemm_split<<<gg(LV, DM, NB), 256, GEMM_SMEM>>>(p12h, p12l, aTh, aTl, nullptr, out1,
        nullptr, nullptr, LV, DM, LA,
        (long)LV * (LA / 2), (long)DM * (LA / 2), (long)LV * DM, 1.f, 1);   // += c_va
    gemm_split<<<gg(LA, DM, NB), 256, GEMM_SMEM>>>(p21h, p21l, vTh, vTl, nullptr, out3,
        nullptr, nullptr, LA, DM, LV,
        (long)LA * (LV / 2), (long)DM * (LV / 2), (long)LA * DM, 1.f, 0);   // c_av

    // ==== pair C: act (192, 128) x det (320, 256) ====
    gemm_split<<<gg(LA, LD, NB), 256, GEMM_SMEM>>>(ah, al, dh, dl, nullptr, S,
        nullptr, nullptr, LA, LD, DM,
        (long)LA * (DM / 2), (long)LD * (DM / 2), (long)LA * LD, 0.125f, 0);
    softmax21<<<dim3(LD / 32, NB), 256>>>(S, ma, p21h, p21l, LA, LD, CA, CD);
    softmax12<LD><<<dim3(LA / 8, NB), 256>>>(S, md, p12h, p12l, LA, CA, CD);
    gemm_split<<<gg(LA, DM, NB), 256, GEMM_SMEM>>>(p12h, p12l, dTh, dTl, nullptr, out3,
        nullptr, nullptr, LA, DM, LD,
        (long)LA * (LD / 2), (long)DM * (LD / 2), (long)LA * DM, 1.f, 1);   // += c_ad
    gemm_split<<<gg(LD, DM, NB), 256, GEMM_SMEM>>>(p21h, p21l, aTh, aTl, nullptr, out2,
        nullptr, nullptr, LD, DM, LA,
        (long)LD * (LA / 2), (long)DM * (LA / 2), (long)LD * DM, 1.f, 1);   // += c_da
}